// round 14
// baseline (speedup 1.0000x reference)
#include <cuda_runtime.h>
#include <cstdint>
#include <math.h>

#define NROWS   4096
#define HDIM    768
#define KDIM    192
#define VOCAB   50257
#define VT64    786            /* tiles of 64 cols */
#define VPAD    (VT64*64)      /* 50304 */
#define NSPLIT  9
#define TOPK    10
#define NCAND   24

#define RSTR    208            /* int8 row stride bytes (192 + 16 pad); 13x16B */
#define CSTR    34             /* C row stride (ints) */

#define SC_X    0.003f
#define SC_E    0.00075f
#define DEQ     (SC_X * SC_E)  /* 2.25e-6 */

/* SMEM: A 26624 | B0 13312 | B1 13312 | C 17408 => 70656, 2 CTAs/SM */
#define SM_A    0
#define SM_B0   26624
#define SM_B1   39936
#define SM_C    53248
#define SM_TOTAL 70656

/* ---------------- scratch ------------------------------------------------- */
__device__ int8_t g_xq[NROWS * KDIM];
__device__ int8_t g_eq[(size_t)VPAD * KDIM];
__device__ float  g_ered[(size_t)VPAD * KDIM];
__device__ float  g_psum[NSPLIT * NROWS];
__device__ float  g_pval[NSPLIT * NROWS * TOPK];
__device__ int    g_pidx[NSPLIT * NROWS * TOPK];

__device__ __forceinline__ uint32_t smem_u32(const void* p) {
    uint32_t a;
    asm("{ .reg .u64 t; cvta.to.shared.u64 t, %1; cvt.u32.u64 %0, t; }" : "=r"(a) : "l"(p));
    return a;
}

#define LDSM4(R, a) \
    asm volatile("ldmatrix.sync.aligned.m8n8.x4.shared.b16 {%0,%1,%2,%3}, [%4];" \
        : "=r"((R)[0]), "=r"((R)[1]), "=r"((R)[2]), "=r"((R)[3]) : "r"(a))

#define IMMA(C, A, b0, b1) \
    asm volatile("mma.sync.aligned.m16n8k32.row.col.s32.s8.s8.s32 " \
        "{%0,%1,%2,%3}, {%4,%5,%6,%7}, {%8,%9}, {%0,%1,%2,%3};" \
        : "+r"((C)[0]), "+r"((C)[1]), "+r"((C)[2]), "+r"((C)[3]) \
        : "r"((A)[0]), "r"((A)[1]), "r"((A)[2]), "r"((A)[3]), "r"(b0), "r"(b1))

#define CP_ASYNC16(dst, src) \
    asm volatile("cp.async.cg.shared.global [%0], [%1], 16;" :: "r"(dst), "l"(src) : "memory")
#define CP_COMMIT()  asm volatile("cp.async.commit_group;" ::: "memory")
#define CP_WAIT1()   asm volatile("cp.async.wait_group 1;" ::: "memory")

#define TOPK_INSERT(TV, TI, THR, sv, col) do {       \
    float _mv = TV[0]; int _mi = 0;                  \
    _Pragma("unroll")                                 \
    for (int _q = 1; _q < TOPK; _q++)                \
        if (TV[_q] < _mv) { _mv = TV[_q]; _mi = _q; }\
    _Pragma("unroll")                                 \
    for (int _q = 0; _q < TOPK; _q++)                \
        if (_q == _mi) { TV[_q] = (sv); TI[_q] = (col); } \
    float _nt = TV[0];                               \
    _Pragma("unroll")                                 \
    for (int _q = 1; _q < TOPK; _q++) _nt = fminf(_nt, TV[_q]); \
    THR = _nt;                                       \
} while (0)

__device__ __forceinline__ uint32_t pack4(float a0, float a1, float a2, float a3,
                                          float inv) {
    int q0 = __float2int_rn(a0 * inv); q0 = max(-127, min(127, q0));
    int q1 = __float2int_rn(a1 * inv); q1 = max(-127, min(127, q1));
    int q2 = __float2int_rn(a2 * inv); q2 = max(-127, min(127, q2));
    int q3 = __float2int_rn(a3 * inv); q3 = max(-127, min(127, q3));
    return (uint32_t)(q0 & 0xFF) | ((uint32_t)(q1 & 0xFF) << 8) |
           ((uint32_t)(q2 & 0xFF) << 16) | ((uint32_t)q3 << 24);
}

/* ---------------- kernel 0: compact + int8 quantize + fp32 e_red ---------- */
__global__ void compact_kernel(const float* __restrict__ x,
                               const float* __restrict__ emb) {
    int stride = gridDim.x * blockDim.x;
    int i0 = blockIdx.x * blockDim.x + threadIdx.x;

    for (int j = i0; j < NROWS * 12; j += stride) {
        int r = j / 12, u = j - r * 12;
        const float* p = x + r * HDIM + u * 64;
        float a[16];
        #pragma unroll
        for (int i = 0; i < 16; i++) a[i] = 4.0f * p[i * 4];
        uint4 pk;
        pk.x = pack4(a[0], a[1], a[2], a[3],   1.0f / SC_X);
        pk.y = pack4(a[4], a[5], a[6], a[7],   1.0f / SC_X);
        pk.z = pack4(a[8], a[9], a[10], a[11], 1.0f / SC_X);
        pk.w = pack4(a[12], a[13], a[14], a[15], 1.0f / SC_X);
        *(uint4*)&g_xq[r * KDIM + u * 16] = pk;
    }
    for (int j = i0; j < VPAD * 12; j += stride) {
        int v = j / 12, u = j - v * 12;
        float a[16];
        if (v < VOCAB) {
            const float* p = emb + (size_t)v * HDIM + u * 64;
            #pragma unroll
            for (int i = 0; i < 16; i++) a[i] = p[i * 4];
        } else {
            #pragma unroll
            for (int i = 0; i < 16; i++) a[i] = 0.0f;
        }
        uint4 pk;
        pk.x = pack4(a[0], a[1], a[2], a[3],   1.0f / SC_E);
        pk.y = pack4(a[4], a[5], a[6], a[7],   1.0f / SC_E);
        pk.z = pack4(a[8], a[9], a[10], a[11], 1.0f / SC_E);
        pk.w = pack4(a[12], a[13], a[14], a[15], 1.0f / SC_E);
        *(uint4*)&g_eq[(size_t)v * KDIM + u * 16] = pk;
        float* er = &g_ered[(size_t)v * KDIM + u * 16];
        #pragma unroll
        for (int i = 0; i < 4; i++)
            *(float4*)&er[i * 4] = make_float4(a[4*i], a[4*i+1], a[4*i+2], a[4*i+3]);
    }
}

/* ---------------- kernel 1: hybrid IMMA + dp4a screening ------------------ */
/* warps 0-3: IMMA cols [vbase, vbase+32); warps 4-7: dp4a cols [+32, +64).  */
__global__ __launch_bounds__(256, 2) void main_kernel() {
    extern __shared__ char smem[];
    uint32_t sb = smem_u32(smem);
    int* C_s = (int*)(smem + SM_C);

    int tid = threadIdx.x;
    int wid = tid >> 5, lane = tid & 31;
    int rb = blockIdx.x & 31, vs = blockIdx.x >> 5;
    int rowBase = rb * 128;

    /* resident A tile: 128 rows x 192 int8, stride 208B */
    for (int j = tid; j < 1664; j += 256) {
        int r = j / 13, u = j - r * 13;
        if (u < 12) {
            uint4 v = *(const uint4*)&g_xq[(rowBase + r) * KDIM + u * 16];
            *(uint4*)(smem + SM_A + r * RSTR + u * 16) = v;
        }
    }

    /* tensor addressing (R11-validated fragment math, m32 per warp) */
    uint32_t aptr0 = sb + SM_A + (uint32_t)((wid * 32 + (lane & 15)) * RSTR
                                            + ((lane >> 4) & 1) * 16);
    uint32_t aptr1 = aptr0 + 16 * RSTR;
    uint32_t bbase = (uint32_t)((((lane & 7) + ((lane >> 4) & 1) * 8)) * RSTR
                                + ((lane >> 3) & 1) * 16);

    int dt = tid - 128;                 /* dp4a thread's row (warps 4-7) */

    float sA = 0.f, sB = 0.f;           /* score moments (int units) */
    float thr = -1e30f;
    float tv[TOPK]; int ti_[TOPK];
    #pragma unroll
    for (int q = 0; q < TOPK; q++) { tv[q] = -1e30f; ti_[q] = 0; }

    int t0 = (vs * VT64) / NSPLIT;
    int t1 = ((vs + 1) * VT64) / NSPLIT;

    /* prologue: tiles t0 -> B0, t0+1 -> B1 */
    #pragma unroll
    for (int pf = 0; pf < 2; ++pf) {
        int tt = t0 + pf;
        if (tt < t1) {
            uint32_t Bb = sb + SM_B0 + (uint32_t)pf * 13312u;
            int vbase = tt * 64;
            for (int i = tid; i < 832; i += 256) {
                int r = i / 13, u = i - r * 13;
                if (u < 12)
                    CP_ASYNC16(Bb + (uint32_t)(r * RSTR + u * 16),
                               (const char*)&g_eq[(size_t)(vbase + r) * KDIM + u * 16]);
            }
        }
        CP_COMMIT();
    }

    for (int t = t0; t < t1; ++t) {
        int s = (t - t0) & 1;
        int vbase = t * 64;
        uint32_t Bb = sb + SM_B0 + (uint32_t)s * 13312u;

        CP_WAIT1();
        __syncthreads();               /* B[s] ready */

        int c0[4][4], c1[4][4];        /* tensor accumulators (warps 0-3) */
        int acc[32];                   /* dp4a accumulators (warps 4-7) */

        if (tid < 128) {
            /* ---- IMMA: m32n32, 6 k32 steps ---- */
            #pragma unroll
            for (int ni = 0; ni < 4; ni++)
                #pragma unroll
                for (int q = 0; q < 4; q++) { c0[ni][q] = 0; c1[ni][q] = 0; }
            uint32_t bptr = Bb + bbase;
            #pragma unroll
            for (int ks = 0; ks < 6; ++ks) {
                uint32_t koff = (uint32_t)ks * 32u;
                uint32_t a0[4], a1[4];
                LDSM4(a0, aptr0 + koff);
                LDSM4(a1, aptr1 + koff);
                #pragma unroll
                for (int j = 0; j < 2; ++j) {
                    uint32_t b[4];
                    LDSM4(b, bptr + (uint32_t)(j * 16 * RSTR) + koff);
                    IMMA(c0[2*j],   a0, b[0], b[1]);
                    IMMA(c0[2*j+1], a0, b[2], b[3]);
                    IMMA(c1[2*j],   a1, b[0], b[1]);
                    IMMA(c1[2*j+1], a1, b[2], b[3]);
                }
            }
        } else {
            /* ---- dp4a: row dt, cols [vbase+32, vbase+64) ---- */
            #pragma unroll
            for (int c = 0; c < 32; c++) acc[c] = 0;
            const int4* xrow = (const int4*)(smem + SM_A + dt * RSTR);
            #pragma unroll 1
            for (int uc = 0; uc < 12; ++uc) {
                int4 xq = xrow[uc];
                #pragma unroll
                for (int c = 0; c < 32; ++c) {
                    int4 eq = *(const int4*)(smem + (Bb - sb) + (32 + c) * RSTR + uc * 16);
                    acc[c] = __dp4a(xq.x, eq.x, acc[c]);
                    acc[c] = __dp4a(xq.y, eq.y, acc[c]);
                    acc[c] = __dp4a(xq.z, eq.z, acc[c]);
                    acc[c] = __dp4a(xq.w, eq.w, acc[c]);
                }
            }
        }
        __syncthreads();               /* everyone done reading B[s] */

        /* prefetch tile t+2 into B[s] */
        if (t + 2 < t1) {
            int nvb = (t + 2) * 64;
            for (int i = tid; i < 832; i += 256) {
                int r = i / 13, u = i - r * 13;
                if (u < 12)
                    CP_ASYNC16(Bb + (uint32_t)(r * RSTR + u * 16),
                               (const char*)&g_eq[(size_t)(nvb + r) * KDIM + u * 16]);
            }
        }
        CP_COMMIT();

        if (tid < 128) {
            /* store C (warp-local rows), then epilogue own row */
            int r0 = wid * 32 + (lane >> 2);
            int cc = (lane & 3) * 2;
            #pragma unroll
            for (int ni = 0; ni < 4; ni++) {
                int col = ni * 8 + cc;
                *(int2*)&C_s[r0 * CSTR + col]        = make_int2(c0[ni][0], c0[ni][1]);
                *(int2*)&C_s[(r0 + 8) * CSTR + col]  = make_int2(c0[ni][2], c0[ni][3]);
                *(int2*)&C_s[(r0 + 16) * CSTR + col] = make_int2(c1[ni][0], c1[ni][1]);
                *(int2*)&C_s[(r0 + 24) * CSTR + col] = make_int2(c1[ni][2], c1[ni][3]);
            }
            __syncwarp();
            int vlim = VOCAB - vbase;
            int cnt = vlim < 32 ? (vlim < 0 ? 0 : vlim) : 32;
            const int* crow = &C_s[tid * CSTR];
            for (int c2 = 0; c2 < cnt; ++c2) {
                float cf = (float)crow[c2];
                sA += cf; sB = fmaf(cf, cf, sB);
                if (cf > thr) TOPK_INSERT(tv, ti_, thr, cf, vbase + c2);
            }
        } else {
            int vlim = VOCAB - vbase - 32;
            int cnt = vlim < 32 ? (vlim < 0 ? 0 : vlim) : 32;
            for (int c2 = 0; c2 < cnt; ++c2) {
                float cf = (float)acc[c2];
                sA += cf; sB = fmaf(cf, cf, sB);
                if (cf > thr) TOPK_INSERT(tv, ti_, thr, cf, vbase + 32 + c2);
            }
        }
    }

    /* ---- merge tensor-half and dp4a-half per row ------------------------- */
    __syncthreads();
    float* msv = (float*)C_s;                  /* [128][21] */
    int*   msi = (int*)msv;
    if (tid >= 128) {
        int sbase = dt * 21;
        #pragma unroll
        for (int q = 0; q < TOPK; q++) { msv[sbase + q] = tv[q]; msi[sbase + 10 + q] = ti_[q]; }
        msv[sbase + 20] = fmaf(0.5f * DEQ * DEQ, sB, DEQ * sA);
    }
    __syncthreads();
    if (tid < 128) {
        int sbase = tid * 21;
        #pragma unroll
        for (int q2 = 0; q2 < TOPK; q2++) {
            float v = msv[sbase + q2];
            if (v > thr) {
                int id = msi[sbase + 10 + q2];
                TOPK_INSERT(tv, ti_, thr, v, id);
            }
        }
        int base = vs * NROWS + rowBase + tid;
        g_psum[base] = fmaf(0.5f * DEQ * DEQ, sB, DEQ * sA) + msv[sbase + 20];
        #pragma unroll
        for (int q = 0; q < TOPK; q++) {
            g_pval[base * TOPK + q] = DEQ * tv[q];
            g_pidx[base * TOPK + q] = ti_[q];
        }
    }
}

/* ---------------- kernel 2: merge + fp32 refine + exact rescoring --------- */
__global__ __launch_bounds__(256) void rescore_kernel(const float* __restrict__ x,
                                                      const float* __restrict__ emb,
                                                      float* __restrict__ out) {
    int row = blockIdx.x;
    __shared__ float4 xs4[KDIM];
    __shared__ float  xr[KDIM];
    __shared__ float  pool_v[NSPLIT * TOPK];
    __shared__ int    pool_i[NSPLIT * TOPK];
    __shared__ float  cv[NCAND];
    __shared__ int    ci[NCAND];
    __shared__ float  rlg[NCAND];
    __shared__ float  rs10[TOPK];
    __shared__ int    si10[TOPK];
    __shared__ float  lgx[TOPK];
    __shared__ float  sS[1];
    int tid = threadIdx.x;
    int w = tid >> 5, lane = tid & 31;

    if (tid < KDIM) {
        float4 v = ((const float4*)(x + (size_t)row * HDIM))[tid];
        xs4[tid] = v;
        xr[tid] = 4.0f * v.x;
    }
    if (tid < NSPLIT * TOPK) {
        int p = tid / TOPK, q = tid - p * TOPK;
        int base = p * NROWS + row;
        pool_v[tid] = g_pval[base * TOPK + q];
        pool_i[tid] = g_pidx[base * TOPK + q];
    }
    if (tid == 224) {
        float S = (float)VOCAB;
        for (int p = 0; p < NSPLIT; p++) S += g_psum[p * NROWS + row];
        sS[0] = S;
    }
    __syncthreads();

    if (tid < NSPLIT * TOPK) {
        float v = pool_v[tid];
        int rank = 0;
        for (int u = 0; u < NSPLIT * TOPK; u++) {
            float vu = pool_v[u];
            rank += (vu > v) || (vu == v && u < tid);
        }
        if (rank < NCAND) { cv[rank] = v; ci[rank] = pool_i[tid]; }
    }
    __syncthreads();

    #pragma unroll
    for (int cc = w; cc < NCAND; cc += 8) {
        const float* e = &g_ered[(size_t)ci[cc] * KDIM];
        float sum = 0.0f;
        #pragma unroll
        for (int j = lane; j < KDIM; j += 32)
            sum = fmaf(xr[j], e[j], sum);
        #pragma unroll
        for (int off = 16; off; off >>= 1) sum += __shfl_xor_sync(0xffffffffu, sum, off);
        if (lane == 0) rlg[cc] = sum;
    }
    __syncthreads();

    if (tid < NCAND) {
        float v = rlg[tid];
        int rank = 0;
        for (int u = 0; u < NCAND; u++) {
            float vu = rlg[u];
            rank += (vu > v) || (vu == v && u < tid);
        }
        if (rank < TOPK) { rs10[rank] = v; si10[rank] = ci[tid]; }
    }
    __syncthreads();

    for (int cc = w; cc < TOPK; cc += 8) {
        const float4* e4 = (const float4*)(emb + (size_t)si10[cc] * HDIM);
        float sum = 0.0f;
        #pragma unroll
        for (int j = lane; j < KDIM; j += 32) {
            float4 a = xs4[j];
            float4 b = e4[j];
            sum = fmaf(a.x, b.x, fmaf(a.y, b.y, fmaf(a.z, b.z, fmaf(a.w, b.w, sum))));
        }
        #pragma unroll
        for (int off = 16; off; off >>= 1) sum += __shfl_xor_sync(0xffffffffu, sum, off);
        if (lane == 0) lgx[cc] = sum;
    }
    __syncthreads();

    if (tid == 0) {
        float lm = lgx[0];
        #pragma unroll
        for (int k = 1; k < TOPK; k++) lm = fmaxf(lm, lgx[k]);
        float se = 0.0f; float ev[TOPK];
        #pragma unroll
        for (int k = 0; k < TOPK; k++) { ev[k] = expf(lgx[k] - lm); se += ev[k]; }
        float S = sS[0];
        float best = -1e30f;
        #pragma unroll
        for (int k = 0; k < TOPK; k++) {
            float sc = 0.5f * (ev[k] / se + expf(rs10[k]) / S);
            best = fmaxf(best, sc);
        }
        out[row] = best;
    }
}

/* ---------------- launch -------------------------------------------------- */
extern "C" void kernel_launch(void* const* d_in, const int* in_sizes, int n_in,
                              void* d_out, int out_size) {
    (void)n_in; (void)out_size;
    const float* x   = (const float*)d_in[0];
    const float* emb = (const float*)d_in[1];
    if (in_sizes[0] != NROWS * HDIM) { const float* t = x; x = emb; emb = t; }
    float* out = (float*)d_out;

    cudaFuncSetAttribute(main_kernel, cudaFuncAttributeMaxDynamicSharedMemorySize, SM_TOTAL);

    compact_kernel<<<1024, 256>>>(x, emb);
    main_kernel<<<32 * NSPLIT, 256, SM_TOTAL>>>();
    rescore_kernel<<<NROWS, 256>>>(x, emb, out);
}